// round 1
// baseline (speedup 1.0000x reference)
#include <cuda_runtime.h>
#include <math.h>

// Problem dims
#define Dd 32
#define Tt 32
#define Ll 64
#define Ee 300
#define Hh 256
#define G3 768      // 3*H
#define Uu 512
#define B1 1024     // D*T  (word-level batch)
#define M1 65536    // B1*L (tokens)
#define N1 1536     // fwd 768 + bwd 768 gate outputs
#define M2 1024     // D*T rows for layer-2 input proj

// Scratch (allocation-free rule: __device__ globals)
__device__ float g_xp1[(size_t)M1 * N1];       // 402.7 MB: word-level input projections
__device__ float g_xp2[(size_t)M2 * N1];       // 6.3 MB : dialog-level input projections
__device__ float g_h1[2][2][B1 * Hh];          // [dir][parity][B1*H]
__device__ float g_h2[2][2][Dd * Hh];          // [dir][parity][D*H]

// ---------------------------------------------------------------------------
// Zero the parity-0 (and all) hidden-state buffers. Re-run every call so the
// launch is deterministic and graph-replayable.
// ---------------------------------------------------------------------------
__global__ void k_zero() {
    const int n1 = 2 * 2 * B1 * Hh;
    const int n2 = 2 * 2 * Dd * Hh;
    float* p1 = &g_h1[0][0][0];
    float* p2 = &g_h2[0][0][0];
    for (int i = blockIdx.x * blockDim.x + threadIdx.x; i < n1 + n2;
         i += gridDim.x * blockDim.x) {
        if (i < n1) p1[i] = 0.0f;
        else        p2[i - n1] = 0.0f;
    }
}

// ---------------------------------------------------------------------------
// Layer-1 input projection with fused embedding gather:
//   g_xp1[m][n] = b_ih[n] + sum_k embed[tokens[m]][k] * W_ih[n][k]
// n in [0,768) -> forward weights, [768,1536) -> backward weights.
// Tile: 64x64, BK=32, 256 threads, 4x4 micro-tile.
// ---------------------------------------------------------------------------
__global__ __launch_bounds__(256) void k_inproj1(
    const int*   __restrict__ tokens,
    const float* __restrict__ embed,
    const float* __restrict__ wf, const float* __restrict__ bf,
    const float* __restrict__ wb, const float* __restrict__ bb)
{
    __shared__ float As[64][33];
    __shared__ float Bs[64][33];
    __shared__ int   toks[64];

    const int bm  = blockIdx.y * 64;
    const int bn  = blockIdx.x * 64;
    const int tid = threadIdx.x;

    if (tid < 64) toks[tid] = tokens[bm + tid];
    __syncthreads();

    float acc[4][4] = {};
    const int row0 = (tid / 16) * 4;
    const int col0 = (tid % 16) * 4;

    for (int k0 = 0; k0 < Ee; k0 += 32) {
        // A tile (gathered embedding rows)
        for (int i = tid; i < 64 * 32; i += 256) {
            int r = i >> 5, k = i & 31;
            float v = 0.0f;
            if (k0 + k < Ee) v = embed[(size_t)toks[r] * Ee + k0 + k];
            As[r][k] = v;
        }
        // B tile (gate weight rows)
        for (int i = tid; i < 64 * 32; i += 256) {
            int c = i >> 5, k = i & 31;
            int n = bn + c;
            float v = 0.0f;
            if (k0 + k < Ee)
                v = (n < G3) ? wf[n * Ee + k0 + k] : wb[(n - G3) * Ee + k0 + k];
            Bs[c][k] = v;
        }
        __syncthreads();
#pragma unroll
        for (int kk = 0; kk < 32; kk++) {
            float a[4], b[4];
#pragma unroll
            for (int i = 0; i < 4; i++) a[i] = As[row0 + i][kk];
#pragma unroll
            for (int j = 0; j < 4; j++) b[j] = Bs[col0 + j][kk];
#pragma unroll
            for (int i = 0; i < 4; i++)
#pragma unroll
                for (int j = 0; j < 4; j++) acc[i][j] += a[i] * b[j];
        }
        __syncthreads();
    }

#pragma unroll
    for (int i = 0; i < 4; i++) {
#pragma unroll
        for (int j = 0; j < 4; j++) {
            int n = bn + col0 + j;
            int m = bm + row0 + i;
            float bias = (n < G3) ? bf[n] : bb[n - G3];
            g_xp1[(size_t)m * N1 + n] = acc[i][j] + bias;
        }
    }
}

// ---------------------------------------------------------------------------
// Layer-2 input projection: A = h_ns (first half of d_out), K=512, dense.
// ---------------------------------------------------------------------------
__global__ __launch_bounds__(256) void k_inproj2(
    const float* __restrict__ A,   // d_out: h_ns [1024][512]
    const float* __restrict__ wf, const float* __restrict__ bf,
    const float* __restrict__ wb, const float* __restrict__ bb)
{
    __shared__ float As[64][33];
    __shared__ float Bs[64][33];

    const int bm  = blockIdx.y * 64;
    const int bn  = blockIdx.x * 64;
    const int tid = threadIdx.x;

    float acc[4][4] = {};
    const int row0 = (tid / 16) * 4;
    const int col0 = (tid % 16) * 4;

    for (int k0 = 0; k0 < Uu; k0 += 32) {
        for (int i = tid; i < 64 * 32; i += 256) {
            int r = i >> 5, k = i & 31;
            As[r][k] = A[(size_t)(bm + r) * Uu + k0 + k];
        }
        for (int i = tid; i < 64 * 32; i += 256) {
            int c = i >> 5, k = i & 31;
            int n = bn + c;
            Bs[c][k] = (n < G3) ? wf[n * Uu + k0 + k] : wb[(n - G3) * Uu + k0 + k];
        }
        __syncthreads();
#pragma unroll
        for (int kk = 0; kk < 32; kk++) {
            float a[4], b[4];
#pragma unroll
            for (int i = 0; i < 4; i++) a[i] = As[row0 + i][kk];
#pragma unroll
            for (int j = 0; j < 4; j++) b[j] = Bs[col0 + j][kk];
#pragma unroll
            for (int i = 0; i < 4; i++)
#pragma unroll
                for (int j = 0; j < 4; j++) acc[i][j] += a[i] * b[j];
        }
        __syncthreads();
    }

#pragma unroll
    for (int i = 0; i < 4; i++) {
#pragma unroll
        for (int j = 0; j < 4; j++) {
            int n = bn + col0 + j;
            int m = bm + row0 + i;
            float bias = (n < G3) ? bf[n] : bb[n - G3];
            g_xp2[(size_t)m * N1 + n] = acc[i][j] + bias;
        }
    }
}

// ---------------------------------------------------------------------------
// Word-level GRU step (one launch per time step, both directions).
// Block: 64 batch rows x 32 hidden cols, computes the 3 gate dot products
// gh = h @ W_hh^T (+ b_hh) then the gate nonlinearity and h update.
// grid = (8 col-chunks, 16 row-tiles, 2 dirs), 256 threads, micro 4x2 (x3 gates).
// ---------------------------------------------------------------------------
__global__ __launch_bounds__(256) void k_step1(
    const float* __restrict__ whf, const float* __restrict__ whb,
    const float* __restrict__ bhf, const float* __restrict__ bhb,
    int t, float* __restrict__ out)
{
    const int dir = blockIdx.z;
    const float* W  = dir ? whb : whf;
    const float* bh = dir ? bhb : bhf;
    const int rowbase = blockIdx.y * 64;
    const int colbase = blockIdx.x * 32;
    const int p = t & 1;
    const float* __restrict__ hin = g_h1[dir][p];
    float* __restrict__ hout      = g_h1[dir][p ^ 1];

    __shared__ float hs[64][33];
    __shared__ float ws[3][32][33];

    const int tid = threadIdx.x;
    float acc[4][2][3] = {};
    const int r0 = (tid / 16) * 4;
    const int c0 = (tid % 16) * 2;

    for (int k0 = 0; k0 < Hh; k0 += 32) {
        for (int i = tid; i < 64 * 32; i += 256) {
            int r = i >> 5, k = i & 31;
            hs[r][k] = hin[(rowbase + r) * Hh + k0 + k];
        }
        for (int i = tid; i < 3 * 32 * 32; i += 256) {
            int g = i >> 10, c = (i >> 5) & 31, k = i & 31;
            ws[g][c][k] = W[(g * Hh + colbase + c) * Hh + k0 + k];
        }
        __syncthreads();
#pragma unroll
        for (int kk = 0; kk < 32; kk++) {
            float a[4];
#pragma unroll
            for (int i = 0; i < 4; i++) a[i] = hs[r0 + i][kk];
            float w[2][3];
#pragma unroll
            for (int j = 0; j < 2; j++) {
                w[j][0] = ws[0][c0 + j][kk];
                w[j][1] = ws[1][c0 + j][kk];
                w[j][2] = ws[2][c0 + j][kk];
            }
#pragma unroll
            for (int i = 0; i < 4; i++)
#pragma unroll
                for (int j = 0; j < 2; j++) {
                    acc[i][j][0] += a[i] * w[j][0];
                    acc[i][j][1] += a[i] * w[j][1];
                    acc[i][j][2] += a[i] * w[j][2];
                }
        }
        __syncthreads();
    }

    const int l = dir ? (Ll - 1 - t) : t;
#pragma unroll
    for (int i = 0; i < 4; i++) {
#pragma unroll
        for (int j = 0; j < 2; j++) {
            int row = rowbase + r0 + i;
            int col = colbase + c0 + j;
            const float* xp = &g_xp1[((size_t)row * Ll + l) * N1 + dir * G3];
            float xr = xp[col], xz = xp[Hh + col], xn = xp[2 * Hh + col];
            float hr = acc[i][j][0] + bh[col];
            float hz = acc[i][j][1] + bh[Hh + col];
            float hn = acc[i][j][2] + bh[2 * Hh + col];
            float rg = 1.0f / (1.0f + expf(-(xr + hr)));
            float zg = 1.0f / (1.0f + expf(-(xz + hz)));
            float ng = tanhf(xn + rg * hn);
            float hold = hin[row * Hh + col];
            float hnew = (1.0f - zg) * ng + zg * hold;
            hout[row * Hh + col] = hnew;
            if (t == Ll - 1)  // final hidden -> h_ns output
                out[row * Uu + dir * Hh + col] = hnew;
        }
    }
}

// ---------------------------------------------------------------------------
// Dialog-level GRU step. B=32 dialogs, writes the per-step output into the
// second half of d_out (backward dir writes at reversed position).
// grid = (32 col-chunks of 8, 1, 2 dirs), 128 threads, micro 2 rows x 1 col.
// ---------------------------------------------------------------------------
__global__ __launch_bounds__(128) void k_step2(
    const float* __restrict__ whf, const float* __restrict__ whb,
    const float* __restrict__ bhf, const float* __restrict__ bhb,
    int t, float* __restrict__ out)
{
    const int dir = blockIdx.z;
    const float* W  = dir ? whb : whf;
    const float* bh = dir ? bhb : bhf;
    const int colbase = blockIdx.x * 8;
    const int p = t & 1;
    const float* __restrict__ hin = g_h2[dir][p];
    float* __restrict__ hout      = g_h2[dir][p ^ 1];

    __shared__ float hs[32][33];
    __shared__ float ws[3][8][33];

    const int tid = threadIdx.x;
    float acc[2][3] = {};
    const int r0 = (tid / 8) * 2;
    const int c0 = tid % 8;

    for (int k0 = 0; k0 < Hh; k0 += 32) {
        for (int i = tid; i < 32 * 32; i += 128) {
            int r = i >> 5, k = i & 31;
            hs[r][k] = hin[r * Hh + k0 + k];
        }
        for (int i = tid; i < 3 * 8 * 32; i += 128) {
            int g = i >> 8, c = (i >> 5) & 7, k = i & 31;
            ws[g][c][k] = W[(g * Hh + colbase + c) * Hh + k0 + k];
        }
        __syncthreads();
#pragma unroll
        for (int kk = 0; kk < 32; kk++) {
            float a0 = hs[r0][kk], a1 = hs[r0 + 1][kk];
            float w0 = ws[0][c0][kk], w1 = ws[1][c0][kk], w2 = ws[2][c0][kk];
            acc[0][0] += a0 * w0; acc[0][1] += a0 * w1; acc[0][2] += a0 * w2;
            acc[1][0] += a1 * w0; acc[1][1] += a1 * w1; acc[1][2] += a1 * w2;
        }
        __syncthreads();
    }

    const int l = dir ? (Tt - 1 - t) : t;
#pragma unroll
    for (int i = 0; i < 2; i++) {
        int row = r0 + i;              // dialog index
        int col = colbase + c0;
        const float* xp = &g_xp2[((size_t)row * Tt + l) * N1 + dir * G3];
        float xr = xp[col], xz = xp[Hh + col], xn = xp[2 * Hh + col];
        float hr = acc[i][0] + bh[col];
        float hz = acc[i][1] + bh[Hh + col];
        float hn = acc[i][2] + bh[2 * Hh + col];
        float rg = 1.0f / (1.0f + expf(-(xr + hr)));
        float zg = 1.0f / (1.0f + expf(-(xz + hz)));
        float ng = tanhf(xn + rg * hn);
        float hold = hin[row * Hh + col];
        float hnew = (1.0f - zg) * ng + zg * hold;
        hout[row * Hh + col] = hnew;
        out[(size_t)(Dd * Tt * Uu) + ((size_t)row * Tt + l) * Uu + dir * Hh + col] = hnew;
    }
}

// ---------------------------------------------------------------------------
// Launch: zero -> inproj1 -> 64x step1 -> inproj2 -> 32x step2.
// All on the default stream (sequential deps), graph-capturable, no allocs.
// ---------------------------------------------------------------------------
extern "C" void kernel_launch(void* const* d_in, const int* in_sizes, int n_in,
                              void* d_out, int out_size)
{
    (void)in_sizes; (void)n_in; (void)out_size;
    const int*   tokens   = (const int*)  d_in[0];
    const float* embed    = (const float*)d_in[1];
    const float* w_ih_f1  = (const float*)d_in[2];
    const float* w_hh_f1  = (const float*)d_in[3];
    const float* b_ih_f1  = (const float*)d_in[4];
    const float* b_hh_f1  = (const float*)d_in[5];
    const float* w_ih_b1  = (const float*)d_in[6];
    const float* w_hh_b1  = (const float*)d_in[7];
    const float* b_ih_b1  = (const float*)d_in[8];
    const float* b_hh_b1  = (const float*)d_in[9];
    const float* w_ih_f2  = (const float*)d_in[10];
    const float* w_hh_f2  = (const float*)d_in[11];
    const float* b_ih_f2  = (const float*)d_in[12];
    const float* b_hh_f2  = (const float*)d_in[13];
    const float* w_ih_b2  = (const float*)d_in[14];
    const float* w_hh_b2  = (const float*)d_in[15];
    const float* b_ih_b2  = (const float*)d_in[16];
    const float* b_hh_b2  = (const float*)d_in[17];
    float* out = (float*)d_out;

    k_zero<<<128, 256>>>();

    // Word-level input projections (fused embedding gather), fwd+bwd
    k_inproj1<<<dim3(N1 / 64, M1 / 64), 256>>>(tokens, embed,
                                               w_ih_f1, b_ih_f1,
                                               w_ih_b1, b_ih_b1);

    // Word-level recurrence: 64 steps, both directions per launch
    for (int t = 0; t < Ll; t++)
        k_step1<<<dim3(Hh / 32, B1 / 64, 2), 256>>>(w_hh_f1, w_hh_b1,
                                                    b_hh_f1, b_hh_b1, t, out);

    // Dialog-level input projections (reads h_ns from d_out)
    k_inproj2<<<dim3(N1 / 64, M2 / 64), 256>>>(out,
                                               w_ih_f2, b_ih_f2,
                                               w_ih_b2, b_ih_b2);

    // Dialog-level recurrence: 32 steps, writes outputs per step
    for (int t = 0; t < Tt; t++)
        k_step2<<<dim3(Hh / 8, 1, 2), 128>>>(w_hh_f2, w_hh_b2,
                                             b_hh_f2, b_hh_b2, t, out);
}